// round 12
// baseline (speedup 1.0000x reference)
#include <cuda_runtime.h>

#define HH 2048
#define WW 2048
#define TPB 128
#define WARPS (TPB / 32)               // 4
#define CPW 30                         // output columns per warp
#define CPB (WARPS * CPW)              // 120 output columns per block
#define ROWS 23                        // output rows per strip
#define GRID_X ((WW - 2 + CPB - 1) / CPB)    // 18
#define GRID_Y ((HH + ROWS - 1) / ROWS)      // 90
#define NBLOCKS (GRID_X * GRID_Y)            // 1620  (single wave at 11 blocks/SM)

__device__ float g_acc[3];       // zero-initialized at module load; reset by last block
__device__ unsigned g_count;

__global__ __launch_bounds__(TPB) void loss_fused_kernel(
    const float* __restrict__ pred_E,
    const float* __restrict__ pred_v,
    const float* __restrict__ strain,
    float* __restrict__ out)
{
    const int tid  = threadIdx.x;
    const int lane = tid & 31;
    const int warp = tid >> 5;
    const int col  = (blockIdx.x * WARPS + warp) * CPW + lane;  // input column
    const int row0 = blockIdx.y * ROWS;
    const bool col_ok  = (col < WW);
    const bool own_col = (lane < CPW) && col_ok;      // unique owner of this column (for sum E)
    const bool out_col = (lane < CPW) && (col < WW - 2);

    float accx = 0.f, accy = 0.f, accE = 0.f;

    // register ring: rows i (a) and i+1 (b) of the running vertical sums
    float h3E_a = 0.f, h3E_b = 0.f;
    float h3XX_a = 0.f, h3XX_b = 0.f;
    float h3XY_a = 0.f, h3XY_b = 0.f;
    float yy0_a = 0.f, yy0_b = 0.f, yy2_a = 0.f, yy2_b = 0.f;
    float xy0_a = 0.f, xy0_b = 0.f, xy2_a = 0.f, xy2_b = 0.f;

    // raw prefetch registers
    float cE, cV, cXX, cYY, cXY;     // current row raw inputs
    {
        const bool ok = col_ok && (row0 < HH);
        const int idx = row0 * WW + col;
        cE  = ok ? pred_E[idx] : 0.f;
        cV  = ok ? pred_v[idx] : 0.f;
        cXX = ok ? strain[3 * idx + 0] : 0.f;
        cYY = ok ? strain[3 * idx + 1] : 0.f;
        cXY = ok ? strain[3 * idx + 2] : 0.f;
    }

    #pragma unroll 2
    for (int k = 0; k < ROWS + 2; ++k) {
        const int r = row0 + k;

        // ---- prefetch raw row r+1 ----
        float nE = 0.f, nV = 0.f, nXX = 0.f, nYY = 0.f, nXY = 0.f;
        if (k < ROWS + 1) {
            const bool ok = (r + 1 < HH) && col_ok;
            const int idx = (r + 1) * WW + col;
            if (ok) {
                nE  = pred_E[idx];
                nV  = pred_v[idx];
                nXX = strain[3 * idx + 0];
                nYY = strain[3 * idx + 1];
                nXY = strain[3 * idx + 2];
            }
        }

        // ---- stress for current row ----
        const float frac = __fdividef(cE, 1.f - cV * cV);
        const float sxx = (cXX + cV * cYY) * frac;
        const float syy = (cV * cXX + cYY) * frac;
        const float sxy = cXY * (1.f - cV) * 0.5f * frac;

        if (own_col && k < ROWS) accE += cE;   // cE==0 beyond grid => safe

        // ---- horizontal gathers via shuffle ----
        const float E1  = __shfl_down_sync(0xFFFFFFFFu, cE,  1);
        const float E2  = __shfl_down_sync(0xFFFFFFFFu, cE,  2);
        const float XX1 = __shfl_down_sync(0xFFFFFFFFu, sxx, 1);
        const float XX2 = __shfl_down_sync(0xFFFFFFFFu, sxx, 2);
        const float XY1 = __shfl_down_sync(0xFFFFFFFFu, sxy, 1);
        const float XY2 = __shfl_down_sync(0xFFFFFFFFu, sxy, 2);
        const float YY2 = __shfl_down_sync(0xFFFFFFFFu, syy, 2);

        const float h3E  = cE  + E1  + E2;
        const float h3XX = sxx + XX1 + XX2;
        const float h3XY = sxy + XY1 + XY2;

        if (k >= 2) {
            const int i = r - 2;                       // output row
            if (out_col && i < HH - 2) {
                const float Econv = h3E_a + h3E_b + h3E;
                const float fx = (h3XX - h3XX_a)
                               + (xy0_a + xy0_b + sxy) - (xy2_a + xy2_b + XY2);
                const float fy = (yy0_a + yy0_b + syy) - (yy2_a + yy2_b + YY2)
                               + (h3XY - h3XY_a);
                const float inv = __fdividef(1.f, Econv);   // E>0 => Econv>0
                accx += fabsf(fx * inv);
                accy += fabsf(fy * inv);
            }
        }

        // rotate rings
        h3E_a  = h3E_b;  h3E_b  = h3E;
        h3XX_a = h3XX_b; h3XX_b = h3XX;
        h3XY_a = h3XY_b; h3XY_b = h3XY;
        yy0_a  = yy0_b;  yy0_b  = syy;
        yy2_a  = yy2_b;  yy2_b  = YY2;
        xy0_a  = xy0_b;  xy0_b  = sxy;
        xy2_a  = xy2_b;  xy2_b  = XY2;

        cE = nE; cV = nV; cXX = nXX; cYY = nYY; cXY = nXY;
    }

    // ---- block reduction ----
    __shared__ float red[WARPS][3];
    __shared__ bool isLast;
    #pragma unroll
    for (int o = 16; o > 0; o >>= 1) {
        accx += __shfl_down_sync(0xFFFFFFFFu, accx, o);
        accy += __shfl_down_sync(0xFFFFFFFFu, accy, o);
        accE += __shfl_down_sync(0xFFFFFFFFu, accE, o);
    }
    if (lane == 0) { red[warp][0] = accx; red[warp][1] = accy; red[warp][2] = accE; }
    __syncthreads();
    if (warp == 0) {
        float ax = (lane < WARPS) ? red[lane][0] : 0.f;
        float ay = (lane < WARPS) ? red[lane][1] : 0.f;
        float aE = (lane < WARPS) ? red[lane][2] : 0.f;
        #pragma unroll
        for (int o = 2; o > 0; o >>= 1) {
            ax += __shfl_down_sync(0xFFFFFFFFu, ax, o);
            ay += __shfl_down_sync(0xFFFFFFFFu, ay, o);
            aE += __shfl_down_sync(0xFFFFFFFFu, aE, o);
        }
        if (lane == 0) {
            atomicAdd(&g_acc[0], ax);
            atomicAdd(&g_acc[1], ay);
            atomicAdd(&g_acc[2], aE);
        }
    }

    // ---- last-block finalize (single-kernel; resets state for next graph replay) ----
    if (tid == 0) {
        __threadfence();
        unsigned prev = atomicAdd(&g_count, 1u);
        isLast = (prev == NBLOCKS - 1);
    }
    __syncthreads();
    if (isLast && tid == 0) {
        const float invM = 1.0f / ((float)(WW - 2) * (float)(HH - 2));
        const float invN = 1.0f / ((float)WW * (float)HH);
        out[0] = g_acc[0] * invM + g_acc[1] * invM
               + fabsf(g_acc[2] * invN - 1.0f) * 0.01f;
        g_acc[0] = 0.f; g_acc[1] = 0.f; g_acc[2] = 0.f;
        g_count = 0u;
    }
}

extern "C" void kernel_launch(void* const* d_in, const int* in_sizes, int n_in,
                              void* d_out, int out_size) {
    const float* pred_E = (const float*)d_in[0];
    const float* pred_v = (const float*)d_in[1];
    const float* strain = (const float*)d_in[2];

    dim3 grid(GRID_X, GRID_Y);   // 18 x 90 = 1620 blocks — single wave at 11 blocks/SM
    loss_fused_kernel<<<grid, TPB>>>(pred_E, pred_v, strain, (float*)d_out);
}

// round 14
// speedup vs baseline: 1.3743x; 1.3743x over previous
#include <cuda_runtime.h>

#define HH 2048
#define WW 2048
#define TPB 256
#define WARPS (TPB / 32)               // 8
#define CPW 30                         // output columns per warp
#define CPB (WARPS * CPW)              // 240 output columns per block
#define ROWS 21                        // output rows per strip
#define GRID_X ((WW - 2 + CPB - 1) / CPB)    // 9
#define GRID_Y ((HH + ROWS - 1) / ROWS)      // 98
#define NBLOCKS (GRID_X * GRID_Y)            // 882  (single wave at 6 blocks/SM)

__device__ float g_acc[3];       // zero-initialized at module load; reset by last block
__device__ unsigned g_count;

__global__ __launch_bounds__(TPB, 6) void loss_fused_kernel(
    const float* __restrict__ pred_E,
    const float* __restrict__ pred_v,
    const float* __restrict__ strain,
    float* __restrict__ out)
{
    const int tid  = threadIdx.x;
    const int lane = tid & 31;
    const int warp = tid >> 5;
    const int col  = (blockIdx.x * WARPS + warp) * CPW + lane;  // input column
    const int row0 = blockIdx.y * ROWS;
    const bool col_ok  = (col < WW);
    const bool own_col = (lane < CPW) && col_ok;      // unique owner of this column (for sum E)
    const bool out_col = (lane < CPW) && (col < WW - 2);

    float accx = 0.f, accy = 0.f, accE = 0.f;

    // register ring: rows i (a) and i+1 (b) of the running vertical sums
    float h3E_a = 0.f, h3E_b = 0.f;
    float h3XX_a = 0.f, h3XX_b = 0.f;
    float h3XY_a = 0.f, h3XY_b = 0.f;
    float yy0_a = 0.f, yy0_b = 0.f, yy2_a = 0.f, yy2_b = 0.f;
    float xy0_a = 0.f, xy0_b = 0.f, xy2_a = 0.f, xy2_b = 0.f;

    // raw prefetch registers
    float cE, cV, cXX, cYY, cXY;     // current row raw inputs
    {
        const bool ok = col_ok && (row0 < HH);
        const int idx = row0 * WW + col;
        cE  = ok ? pred_E[idx] : 0.f;
        cV  = ok ? pred_v[idx] : 0.f;
        cXX = ok ? strain[3 * idx + 0] : 0.f;
        cYY = ok ? strain[3 * idx + 1] : 0.f;
        cXY = ok ? strain[3 * idx + 2] : 0.f;
    }

    #pragma unroll 2
    for (int k = 0; k < ROWS + 2; ++k) {
        const int r = row0 + k;

        // ---- prefetch raw row r+1 ----
        float nE = 0.f, nV = 0.f, nXX = 0.f, nYY = 0.f, nXY = 0.f;
        if (k < ROWS + 1) {
            const bool ok = (r + 1 < HH) && col_ok;
            const int idx = (r + 1) * WW + col;
            if (ok) {
                nE  = pred_E[idx];
                nV  = pred_v[idx];
                nXX = strain[3 * idx + 0];
                nYY = strain[3 * idx + 1];
                nXY = strain[3 * idx + 2];
            }
        }

        // ---- stress for current row ----
        const float frac = __fdividef(cE, 1.f - cV * cV);
        const float sxx = (cXX + cV * cYY) * frac;
        const float syy = (cV * cXX + cYY) * frac;
        const float sxy = cXY * (1.f - cV) * 0.5f * frac;

        if (own_col && k < ROWS) accE += cE;   // cE==0 beyond grid => safe

        // ---- horizontal gathers via shuffle ----
        const float E1  = __shfl_down_sync(0xFFFFFFFFu, cE,  1);
        const float E2  = __shfl_down_sync(0xFFFFFFFFu, cE,  2);
        const float XX1 = __shfl_down_sync(0xFFFFFFFFu, sxx, 1);
        const float XX2 = __shfl_down_sync(0xFFFFFFFFu, sxx, 2);
        const float XY1 = __shfl_down_sync(0xFFFFFFFFu, sxy, 1);
        const float XY2 = __shfl_down_sync(0xFFFFFFFFu, sxy, 2);
        const float YY2 = __shfl_down_sync(0xFFFFFFFFu, syy, 2);

        const float h3E  = cE  + E1  + E2;
        const float h3XX = sxx + XX1 + XX2;
        const float h3XY = sxy + XY1 + XY2;

        if (k >= 2) {
            const int i = r - 2;                       // output row
            if (out_col && i < HH - 2) {
                const float Econv = h3E_a + h3E_b + h3E;
                const float fx = (h3XX - h3XX_a)
                               + (xy0_a + xy0_b + sxy) - (xy2_a + xy2_b + XY2);
                const float fy = (yy0_a + yy0_b + syy) - (yy2_a + yy2_b + YY2)
                               + (h3XY - h3XY_a);
                const float inv = __fdividef(1.f, Econv);   // E>0 => Econv>0
                accx += fabsf(fx * inv);
                accy += fabsf(fy * inv);
            }
        }

        // rotate rings
        h3E_a  = h3E_b;  h3E_b  = h3E;
        h3XX_a = h3XX_b; h3XX_b = h3XX;
        h3XY_a = h3XY_b; h3XY_b = h3XY;
        yy0_a  = yy0_b;  yy0_b  = syy;
        yy2_a  = yy2_b;  yy2_b  = YY2;
        xy0_a  = xy0_b;  xy0_b  = sxy;
        xy2_a  = xy2_b;  xy2_b  = XY2;

        cE = nE; cV = nV; cXX = nXX; cYY = nYY; cXY = nXY;
    }

    // ---- block reduction ----
    __shared__ float red[WARPS][3];
    __shared__ bool isLast;
    #pragma unroll
    for (int o = 16; o > 0; o >>= 1) {
        accx += __shfl_down_sync(0xFFFFFFFFu, accx, o);
        accy += __shfl_down_sync(0xFFFFFFFFu, accy, o);
        accE += __shfl_down_sync(0xFFFFFFFFu, accE, o);
    }
    if (lane == 0) { red[warp][0] = accx; red[warp][1] = accy; red[warp][2] = accE; }
    __syncthreads();
    if (warp == 0) {
        float ax = (lane < WARPS) ? red[lane][0] : 0.f;
        float ay = (lane < WARPS) ? red[lane][1] : 0.f;
        float aE = (lane < WARPS) ? red[lane][2] : 0.f;
        #pragma unroll
        for (int o = 4; o > 0; o >>= 1) {
            ax += __shfl_down_sync(0xFFFFFFFFu, ax, o);
            ay += __shfl_down_sync(0xFFFFFFFFu, ay, o);
            aE += __shfl_down_sync(0xFFFFFFFFu, aE, o);
        }
        if (lane == 0) {
            atomicAdd(&g_acc[0], ax);
            atomicAdd(&g_acc[1], ay);
            atomicAdd(&g_acc[2], aE);
        }
    }

    // ---- last-block finalize (single-kernel; resets state for next graph replay) ----
    if (tid == 0) {
        __threadfence();
        unsigned prev = atomicAdd(&g_count, 1u);
        isLast = (prev == NBLOCKS - 1);
    }
    __syncthreads();
    if (isLast && tid == 0) {
        const float invM = 1.0f / ((float)(WW - 2) * (float)(HH - 2));
        const float invN = 1.0f / ((float)WW * (float)HH);
        out[0] = g_acc[0] * invM + g_acc[1] * invM
               + fabsf(g_acc[2] * invN - 1.0f) * 0.01f;
        g_acc[0] = 0.f; g_acc[1] = 0.f; g_acc[2] = 0.f;
        g_count = 0u;
    }
}

extern "C" void kernel_launch(void* const* d_in, const int* in_sizes, int n_in,
                              void* d_out, int out_size) {
    const float* pred_E = (const float*)d_in[0];
    const float* pred_v = (const float*)d_in[1];
    const float* strain = (const float*)d_in[2];

    dim3 grid(GRID_X, GRID_Y);   // 9 x 98 = 882 blocks — single wave at 6 blocks/SM
    loss_fused_kernel<<<grid, TPB>>>(pred_E, pred_v, strain, (float*)d_out);
}

// round 15
// speedup vs baseline: 1.6140x; 1.1745x over previous
#include <cuda_runtime.h>

#define HH 2048
#define WW 2048
#define TPB 256
#define WARPS (TPB / 32)               // 8
#define CPW 30                         // output columns per warp
#define CPB (WARPS * CPW)              // 240 output columns per block
#define ROWS 21                        // output rows per strip
#define GRID_X ((WW - 2 + CPB - 1) / CPB)    // 9
#define GRID_Y ((HH + ROWS - 1) / ROWS)      // 98
#define NBLOCKS (GRID_X * GRID_Y)            // 882  (single wave at 6 blocks/SM)

__device__ float g_acc[3];       // zero-initialized at module load; reset by last block
__device__ unsigned g_count;

__global__ __launch_bounds__(TPB, 6) void loss_fused_kernel(
    const float* __restrict__ pred_E,
    const float* __restrict__ pred_v,
    const float* __restrict__ strain,
    float* __restrict__ out)
{
    const int tid  = threadIdx.x;
    const int lane = tid & 31;
    const int warp = tid >> 5;
    const int col  = (blockIdx.x * WARPS + warp) * CPW + lane;  // input column
    const int row0 = blockIdx.y * ROWS;
    const bool col_ok  = (col < WW);
    const bool own_col = (lane < CPW) && col_ok;      // unique owner of this column (for sum E)
    const bool out_col = (lane < CPW) && (col < WW - 2);

    float accx = 0.f, accy = 0.f, accE = 0.f;

    // register rings (rows i, i+1 of the vertical 3-window) — 5 quantities only:
    //   h3E, h3XX, h3XY : horizontal 3-sums
    //   d_xy = xy[c] - xy[c+2], d_yy = yy[c] - yy[c+2]  (difference folding)
    float h3E_a = 0.f, h3E_b = 0.f;
    float h3XX_a = 0.f, h3XX_b = 0.f;
    float h3XY_a = 0.f, h3XY_b = 0.f;
    float dxy_a = 0.f, dxy_b = 0.f;
    float dyy_a = 0.f, dyy_b = 0.f;

    // raw prefetch registers
    float cE, cV, cXX, cYY, cXY;     // current row raw inputs
    {
        const bool ok = col_ok && (row0 < HH);
        const int idx = row0 * WW + col;
        cE  = ok ? pred_E[idx] : 0.f;
        cV  = ok ? pred_v[idx] : 0.f;
        cXX = ok ? strain[3 * idx + 0] : 0.f;
        cYY = ok ? strain[3 * idx + 1] : 0.f;
        cXY = ok ? strain[3 * idx + 2] : 0.f;
    }

    #pragma unroll 2
    for (int k = 0; k < ROWS + 2; ++k) {
        const int r = row0 + k;

        // ---- prefetch raw row r+1 ----
        float nE = 0.f, nV = 0.f, nXX = 0.f, nYY = 0.f, nXY = 0.f;
        if (k < ROWS + 1) {
            const bool ok = (r + 1 < HH) && col_ok;
            const int idx = (r + 1) * WW + col;
            if (ok) {
                nE  = pred_E[idx];
                nV  = pred_v[idx];
                nXX = strain[3 * idx + 0];
                nYY = strain[3 * idx + 1];
                nXY = strain[3 * idx + 2];
            }
        }

        // ---- stress for current row ----
        const float frac = __fdividef(cE, 1.f - cV * cV);
        const float sxx = (cXX + cV * cYY) * frac;
        const float syy = (cV * cXX + cYY) * frac;
        const float sxy = cXY * (1.f - cV) * 0.5f * frac;

        if (own_col && k < ROWS) accE += cE;   // cE==0 beyond grid => safe

        // ---- horizontal gathers via shuffle ----
        const float E1  = __shfl_down_sync(0xFFFFFFFFu, cE,  1);
        const float E2  = __shfl_down_sync(0xFFFFFFFFu, cE,  2);
        const float XX1 = __shfl_down_sync(0xFFFFFFFFu, sxx, 1);
        const float XX2 = __shfl_down_sync(0xFFFFFFFFu, sxx, 2);
        const float XY1 = __shfl_down_sync(0xFFFFFFFFu, sxy, 1);
        const float XY2 = __shfl_down_sync(0xFFFFFFFFu, sxy, 2);
        const float YY2 = __shfl_down_sync(0xFFFFFFFFu, syy, 2);

        const float h3E  = cE  + E1  + E2;
        const float h3XX = sxx + XX1 + XX2;
        const float h3XY = sxy + XY1 + XY2;
        const float dxy  = sxy - XY2;          // xy[col] - xy[col+2]
        const float dyy  = syy - YY2;          // yy[col] - yy[col+2]

        if (k >= 2) {
            const int i = r - 2;                       // output row
            if (out_col && i < HH - 2) {
                const float Econv = h3E_a + h3E_b + h3E;
                const float fx = (h3XX - h3XX_a) + (dxy_a + dxy_b + dxy);
                const float fy = (dyy_a + dyy_b + dyy) + (h3XY - h3XY_a);
                const float inv = __fdividef(1.f, Econv);   // E>0 => Econv>0
                accx += fabsf(fx * inv);
                accy += fabsf(fy * inv);
            }
        }

        // rotate rings
        h3E_a  = h3E_b;  h3E_b  = h3E;
        h3XX_a = h3XX_b; h3XX_b = h3XX;
        h3XY_a = h3XY_b; h3XY_b = h3XY;
        dxy_a  = dxy_b;  dxy_b  = dxy;
        dyy_a  = dyy_b;  dyy_b  = dyy;

        cE = nE; cV = nV; cXX = nXX; cYY = nYY; cXY = nXY;
    }

    // ---- block reduction ----
    __shared__ float red[WARPS][3];
    __shared__ bool isLast;
    #pragma unroll
    for (int o = 16; o > 0; o >>= 1) {
        accx += __shfl_down_sync(0xFFFFFFFFu, accx, o);
        accy += __shfl_down_sync(0xFFFFFFFFu, accy, o);
        accE += __shfl_down_sync(0xFFFFFFFFu, accE, o);
    }
    if (lane == 0) { red[warp][0] = accx; red[warp][1] = accy; red[warp][2] = accE; }
    __syncthreads();
    if (warp == 0) {
        float ax = (lane < WARPS) ? red[lane][0] : 0.f;
        float ay = (lane < WARPS) ? red[lane][1] : 0.f;
        float aE = (lane < WARPS) ? red[lane][2] : 0.f;
        #pragma unroll
        for (int o = 4; o > 0; o >>= 1) {
            ax += __shfl_down_sync(0xFFFFFFFFu, ax, o);
            ay += __shfl_down_sync(0xFFFFFFFFu, ay, o);
            aE += __shfl_down_sync(0xFFFFFFFFu, aE, o);
        }
        if (lane == 0) {
            atomicAdd(&g_acc[0], ax);
            atomicAdd(&g_acc[1], ay);
            atomicAdd(&g_acc[2], aE);
        }
    }

    // ---- last-block finalize (single-kernel; resets state for next graph replay) ----
    if (tid == 0) {
        __threadfence();
        unsigned prev = atomicAdd(&g_count, 1u);
        isLast = (prev == NBLOCKS - 1);
    }
    __syncthreads();
    if (isLast && tid == 0) {
        const float invM = 1.0f / ((float)(WW - 2) * (float)(HH - 2));
        const float invN = 1.0f / ((float)WW * (float)HH);
        out[0] = g_acc[0] * invM + g_acc[1] * invM
               + fabsf(g_acc[2] * invN - 1.0f) * 0.01f;
        g_acc[0] = 0.f; g_acc[1] = 0.f; g_acc[2] = 0.f;
        g_count = 0u;
    }
}

extern "C" void kernel_launch(void* const* d_in, const int* in_sizes, int n_in,
                              void* d_out, int out_size) {
    const float* pred_E = (const float*)d_in[0];
    const float* pred_v = (const float*)d_in[1];
    const float* strain = (const float*)d_in[2];

    dim3 grid(GRID_X, GRID_Y);   // 9 x 98 = 882 blocks — single wave at 6 blocks/SM
    loss_fused_kernel<<<grid, TPB>>>(pred_E, pred_v, strain, (float*)d_out);
}

// round 16
// speedup vs baseline: 1.6526x; 1.0239x over previous
#include <cuda_runtime.h>

#define HH 2048
#define WW 2048
#define TPB 256
#define WARPS (TPB / 32)               // 8
#define CPW 30                         // output columns per warp
#define CPB (WARPS * CPW)              // 240 output columns per block
#define ROWS 25                        // output rows per strip
#define GRID_X ((WW - 2 + CPB - 1) / CPB)    // 9
#define GRID_Y ((HH + ROWS - 1) / ROWS)      // 82
#define NBLOCKS (GRID_X * GRID_Y)            // 738  (single wave at 5 blocks/SM)

__device__ float g_acc[3];       // zero-initialized at module load; reset by last block
__device__ unsigned g_count;

__global__ __launch_bounds__(TPB, 5) void loss_fused_kernel(
    const float* __restrict__ pred_E,
    const float* __restrict__ pred_v,
    const float* __restrict__ strain,
    float* __restrict__ out)
{
    const int tid  = threadIdx.x;
    const int lane = tid & 31;
    const int warp = tid >> 5;
    const int col  = (blockIdx.x * WARPS + warp) * CPW + lane;  // input column
    const int row0 = blockIdx.y * ROWS;
    const bool col_ok  = (col < WW);
    const bool own_col = (lane < CPW) && col_ok;
    const bool out_col = (lane < CPW) && (col < WW - 2);

    float accx = 0.f, accy = 0.f, accE = 0.f;

    // 5 rings only (difference-folded)
    float h3E_a = 0.f, h3E_b = 0.f;
    float h3XX_a = 0.f, h3XX_b = 0.f;
    float h3XY_a = 0.f, h3XY_b = 0.f;
    float dxy_a = 0.f, dxy_b = 0.f;
    float dyy_a = 0.f, dyy_b = 0.f;

    // row base pointers (point at row r = row0+k)
    const float* pE = pred_E + row0 * WW + col;
    const float* pV = pred_v + row0 * WW + col;
    const float* pS = strain + 3 * (row0 * WW + col);

    // 2-deep pipeline: c = row r, p1 = row r+1
    float cE=0.f, cV=0.f, cXX=0.f, cYY=0.f, cXY=0.f;
    float pE1=0.f, pV1=0.f, pXX1=0.f, pYY1=0.f, pXY1=0.f;
    if (col_ok) {
        cE  = pE[0];           cV  = pV[0];
        cXX = pS[0];  cYY = pS[1];  cXY = pS[2];
        // row0+1 < HH always (row0 <= 2025)
        pE1  = pE[WW];         pV1  = pV[WW];
        pXX1 = pS[3*WW];  pYY1 = pS[3*WW+1];  pXY1 = pS[3*WW+2];
    }

    #pragma unroll 2
    for (int k = 0; k < ROWS + 2; ++k) {
        const int r = row0 + k;

        // ---- prefetch raw row r+2 (2 iterations ahead of use) ----
        float nE = 0.f, nV = 0.f, nXX = 0.f, nYY = 0.f, nXY = 0.f;
        if (k < ROWS && (r + 2 < HH) && col_ok) {
            nE  = pE[2*WW];       nV  = pV[2*WW];
            nXX = pS[6*WW];  nYY = pS[6*WW+1];  nXY = pS[6*WW+2];
        }
        pE += WW; pV += WW; pS += 3*WW;

        // ---- stress for current row ----
        const float frac = __fdividef(cE, 1.f - cV * cV);
        const float sxx = (cXX + cV * cYY) * frac;
        const float syy = (cV * cXX + cYY) * frac;
        const float sxy = cXY * (1.f - cV) * 0.5f * frac;

        if (own_col && k < ROWS) accE += cE;   // cE==0 beyond grid => safe

        // ---- horizontal gathers via shuffle ----
        const float E1  = __shfl_down_sync(0xFFFFFFFFu, cE,  1);
        const float E2  = __shfl_down_sync(0xFFFFFFFFu, cE,  2);
        const float XX1 = __shfl_down_sync(0xFFFFFFFFu, sxx, 1);
        const float XX2 = __shfl_down_sync(0xFFFFFFFFu, sxx, 2);
        const float XY1 = __shfl_down_sync(0xFFFFFFFFu, sxy, 1);
        const float XY2 = __shfl_down_sync(0xFFFFFFFFu, sxy, 2);
        const float YY2 = __shfl_down_sync(0xFFFFFFFFu, syy, 2);

        const float h3E  = cE  + E1  + E2;
        const float h3XX = sxx + XX1 + XX2;
        const float h3XY = sxy + XY1 + XY2;
        const float dxy  = sxy - XY2;
        const float dyy  = syy - YY2;

        if (k >= 2) {
            const int i = r - 2;                       // output row
            if (out_col && i < HH - 2) {
                const float Econv = h3E_a + h3E_b + h3E;
                const float fx = (h3XX - h3XX_a) + (dxy_a + dxy_b + dxy);
                const float fy = (dyy_a + dyy_b + dyy) + (h3XY - h3XY_a);
                const float inv = __fdividef(1.f, Econv);
                accx += fabsf(fx * inv);
                accy += fabsf(fy * inv);
            }
        }

        // rotate rings
        h3E_a  = h3E_b;  h3E_b  = h3E;
        h3XX_a = h3XX_b; h3XX_b = h3XX;
        h3XY_a = h3XY_b; h3XY_b = h3XY;
        dxy_a  = dxy_b;  dxy_b  = dxy;
        dyy_a  = dyy_b;  dyy_b  = dyy;

        // advance pipeline
        cE = pE1; cV = pV1; cXX = pXX1; cYY = pYY1; cXY = pXY1;
        pE1 = nE; pV1 = nV; pXX1 = nXX; pYY1 = nYY; pXY1 = nXY;
    }

    // ---- block reduction ----
    __shared__ float red[WARPS][3];
    __shared__ bool isLast;
    #pragma unroll
    for (int o = 16; o > 0; o >>= 1) {
        accx += __shfl_down_sync(0xFFFFFFFFu, accx, o);
        accy += __shfl_down_sync(0xFFFFFFFFu, accy, o);
        accE += __shfl_down_sync(0xFFFFFFFFu, accE, o);
    }
    if (lane == 0) { red[warp][0] = accx; red[warp][1] = accy; red[warp][2] = accE; }
    __syncthreads();
    if (warp == 0) {
        float ax = (lane < WARPS) ? red[lane][0] : 0.f;
        float ay = (lane < WARPS) ? red[lane][1] : 0.f;
        float aE = (lane < WARPS) ? red[lane][2] : 0.f;
        #pragma unroll
        for (int o = 4; o > 0; o >>= 1) {
            ax += __shfl_down_sync(0xFFFFFFFFu, ax, o);
            ay += __shfl_down_sync(0xFFFFFFFFu, ay, o);
            aE += __shfl_down_sync(0xFFFFFFFFu, aE, o);
        }
        if (lane == 0) {
            atomicAdd(&g_acc[0], ax);
            atomicAdd(&g_acc[1], ay);
            atomicAdd(&g_acc[2], aE);
        }
    }

    // ---- last-block finalize (resets state for next graph replay) ----
    if (tid == 0) {
        __threadfence();
        unsigned prev = atomicAdd(&g_count, 1u);
        isLast = (prev == NBLOCKS - 1);
    }
    __syncthreads();
    if (isLast && tid == 0) {
        const float invM = 1.0f / ((float)(WW - 2) * (float)(HH - 2));
        const float invN = 1.0f / ((float)WW * (float)HH);
        out[0] = g_acc[0] * invM + g_acc[1] * invM
               + fabsf(g_acc[2] * invN - 1.0f) * 0.01f;
        g_acc[0] = 0.f; g_acc[1] = 0.f; g_acc[2] = 0.f;
        g_count = 0u;
    }
}

extern "C" void kernel_launch(void* const* d_in, const int* in_sizes, int n_in,
                              void* d_out, int out_size) {
    const float* pred_E = (const float*)d_in[0];
    const float* pred_v = (const float*)d_in[1];
    const float* strain = (const float*)d_in[2];

    dim3 grid(GRID_X, GRID_Y);   // 9 x 82 = 738 blocks — single wave at 5 blocks/SM
    loss_fused_kernel<<<grid, TPB>>>(pred_E, pred_v, strain, (float*)d_out);
}

// round 17
// speedup vs baseline: 1.7669x; 1.0692x over previous
#include <cuda_runtime.h>

#define HH 2048
#define WW 2048
#define TPB 256
#define WARPS (TPB / 32)               // 8
#define CPW 30                         // output columns per warp
#define CPB (WARPS * CPW)              // 240
#define ROWS 25                        // output rows per strip
#define GRID_X ((WW - 2 + CPB - 1) / CPB)    // 9
#define GRID_Y ((HH + ROWS - 1) / ROWS)      // 82
#define NBLOCKS (GRID_X * GRID_Y)            // 738  (single wave at 5 blocks/SM)

__device__ float g_acc[2];       // [0]=sum(|fx|+|fy|)/Ec, [1]=sum E ; reset by last block
__device__ unsigned g_count;

struct Rings {
    float h3E_a, h3E_b, h3XX_a, h3XX_b, h3XY_a, h3XY_b;
    float dxy_a, dxy_b, dyy_a, dyy_b;
};

// One stencil row: stress -> shuffles -> (optional) emit, then rotate rings.
// emit/accum_e are compile-time constants in the unrolled fast path.
__device__ __forceinline__ void row_step(
    float cE, float cV, float cXX, float cYY, float cXY,
    Rings& R, bool emit, bool accum_e, bool out_col, bool own_col,
    float& acc, float& accE)
{
    const float frac = __fdividef(cE, 1.f - cV * cV);
    const float sxx = (cXX + cV * cYY) * frac;
    const float syy = (cV * cXX + cYY) * frac;
    const float sxy = cXY * (1.f - cV) * 0.5f * frac;

    if (accum_e && own_col) accE += cE;

    const float E1  = __shfl_down_sync(0xFFFFFFFFu, cE,  1);
    const float E2  = __shfl_down_sync(0xFFFFFFFFu, cE,  2);
    const float XX1 = __shfl_down_sync(0xFFFFFFFFu, sxx, 1);
    const float XX2 = __shfl_down_sync(0xFFFFFFFFu, sxx, 2);
    const float XY1 = __shfl_down_sync(0xFFFFFFFFu, sxy, 1);
    const float XY2 = __shfl_down_sync(0xFFFFFFFFu, sxy, 2);
    const float YY2 = __shfl_down_sync(0xFFFFFFFFu, syy, 2);

    const float h3E  = cE  + E1  + E2;
    const float h3XX = sxx + XX1 + XX2;
    const float h3XY = sxy + XY1 + XY2;
    const float dxy  = sxy - XY2;
    const float dyy  = syy - YY2;

    if (emit && out_col) {
        const float Econv = R.h3E_a + R.h3E_b + h3E;
        const float fx = (h3XX - R.h3XX_a) + (R.dxy_a + R.dxy_b + dxy);
        const float fy = (R.dyy_a + R.dyy_b + dyy) + (h3XY - R.h3XY_a);
        acc += (fabsf(fx) + fabsf(fy)) * __fdividef(1.f, Econv);
    }

    R.h3E_a  = R.h3E_b;  R.h3E_b  = h3E;
    R.h3XX_a = R.h3XX_b; R.h3XX_b = h3XX;
    R.h3XY_a = R.h3XY_b; R.h3XY_b = h3XY;
    R.dxy_a  = R.dxy_b;  R.dxy_b  = dxy;
    R.dyy_a  = R.dyy_b;  R.dyy_b  = dyy;
}

__global__ __launch_bounds__(TPB, 5) void loss_fused_kernel(
    const float* __restrict__ pred_E,
    const float* __restrict__ pred_v,
    const float* __restrict__ strain,
    float* __restrict__ out)
{
    const int tid  = threadIdx.x;
    const int lane = tid & 31;
    const int warp = tid >> 5;
    const int col  = (blockIdx.x * WARPS + warp) * CPW + lane;
    const int colc = (col < WW) ? col : (WW - 1);     // clamped: loads always in-bounds
    const int row0 = blockIdx.y * ROWS;
    const bool own_col = (lane < CPW) && (col < WW);
    const bool out_col = (lane < CPW) && (col < WW - 2);

    const float* pE = pred_E + row0 * WW + colc;
    const float* pV = pred_v + row0 * WW + colc;
    const float* pS = strain + 3 * (row0 * WW + colc);

    float acc = 0.f, accE = 0.f;
    Rings R = {};

    if (row0 + ROWS + 1 < HH) {
        // ---- fast path (81/82 strips): fully unrolled, branch-free, immediate offsets ----
        #pragma unroll
        for (int k = 0; k < ROWS + 2; ++k) {
            const float cE  = pE[k * WW];
            const float cV  = pV[k * WW];
            const float cXX = pS[3 * k * WW];
            const float cYY = pS[3 * k * WW + 1];
            const float cXY = pS[3 * k * WW + 2];
            row_step(cE, cV, cXX, cYY, cXY, R,
                     (k >= 2), (k < ROWS), out_col, own_col, acc, accE);
        }
    } else {
        // ---- boundary path (last strip only): row-clamped loads, runtime guards ----
        #pragma unroll 2
        for (int k = 0; k < ROWS + 2; ++k) {
            const int r  = row0 + k;
            const int ro = ((r < HH) ? r : (HH - 1)) - row0;
            const float cE  = pE[ro * WW];
            const float cV  = pV[ro * WW];
            const float cXX = pS[3 * ro * WW];
            const float cYY = pS[3 * ro * WW + 1];
            const float cXY = pS[3 * ro * WW + 2];
            const bool in = (r < HH);
            row_step(cE, cV, cXX, cYY, cXY, R,
                     (k >= 2) && in, (k < ROWS) && in, out_col, own_col, acc, accE);
        }
    }

    // ---- block reduction (2 values) ----
    __shared__ float red[WARPS][2];
    __shared__ bool isLast;
    #pragma unroll
    for (int o = 16; o > 0; o >>= 1) {
        acc  += __shfl_down_sync(0xFFFFFFFFu, acc,  o);
        accE += __shfl_down_sync(0xFFFFFFFFu, accE, o);
    }
    if (lane == 0) { red[warp][0] = acc; red[warp][1] = accE; }
    __syncthreads();
    if (warp == 0) {
        float a  = (lane < WARPS) ? red[lane][0] : 0.f;
        float aE = (lane < WARPS) ? red[lane][1] : 0.f;
        #pragma unroll
        for (int o = 4; o > 0; o >>= 1) {
            a  += __shfl_down_sync(0xFFFFFFFFu, a,  o);
            aE += __shfl_down_sync(0xFFFFFFFFu, aE, o);
        }
        if (lane == 0) {
            atomicAdd(&g_acc[0], a);
            atomicAdd(&g_acc[1], aE);
        }
    }

    // ---- last-block finalize (resets state for next graph replay) ----
    if (tid == 0) {
        __threadfence();
        unsigned prev = atomicAdd(&g_count, 1u);
        isLast = (prev == NBLOCKS - 1);
    }
    __syncthreads();
    if (isLast && tid == 0) {
        const float invM = 1.0f / ((float)(WW - 2) * (float)(HH - 2));
        const float invN = 1.0f / ((float)WW * (float)HH);
        out[0] = g_acc[0] * invM + fabsf(g_acc[1] * invN - 1.0f) * 0.01f;
        g_acc[0] = 0.f; g_acc[1] = 0.f;
        g_count = 0u;
    }
}

extern "C" void kernel_launch(void* const* d_in, const int* in_sizes, int n_in,
                              void* d_out, int out_size) {
    const float* pred_E = (const float*)d_in[0];
    const float* pred_v = (const float*)d_in[1];
    const float* strain = (const float*)d_in[2];

    dim3 grid(GRID_X, GRID_Y);   // 9 x 82 = 738 blocks — single wave at 5 blocks/SM
    loss_fused_kernel<<<grid, TPB>>>(pred_E, pred_v, strain, (float*)d_out);
}